// round 6
// baseline (speedup 1.0000x reference)
#include <cuda_runtime.h>
#include <cstdint>

#define DEV_INLINE __device__ __forceinline__
typedef unsigned long long ull;

// ---------------- scratch (device globals; no allocations allowed) ----------
__device__ float g_c1[16 * 1024 * 256];            // after conv1 + frame grouping
__device__ float g_c2[16 * 1024 * 256];            // after conv2
__device__ float g_c3[16 * 4096 * 256];            // after tconv
__device__ float g_gx[(size_t)16 * 8 * 4096 * 96]; // gates_x, GRU-CTA-sliced layout
__device__ float g_w2t[512 * 256];                 // W2 transposed: [kk][o]
__device__ float g_wihT[256 * 768];                // W_ih transposed: [c][g]

// ---------------- packed f32x2 helpers --------------------------------------
DEV_INLINE ull dup2(float x) {
    ull r; asm("mov.b64 %0, {%1, %1};" : "=l"(r) : "f"(x)); return r;
}
DEV_INLINE void fma2(ull& d, ull a, ull b) {
    asm("fma.rn.f32x2 %0, %1, %2, %0;" : "+l"(d) : "l"(a), "l"(b));
}
DEV_INLINE void unpack2(ull v, float& x, float& y) {
    asm("mov.b64 {%0, %1}, %2;" : "=f"(x), "=f"(y) : "l"(v));
}
DEV_INLINE ull pack2(float x, float y) {
    ull r; asm("mov.b64 %0, {%1, %2};" : "=l"(r) : "f"(x), "f"(y)); return r;
}

// ---------------- fast activations (MUFU ex2 + rcp; rel err ~1e-6) ----------
DEV_INLINE float fast_tanh(float x) {
    x = fminf(15.f, fmaxf(-15.f, x));
    float e = __expf(2.f * x);
    return __fdividef(e - 1.f, e + 1.f);
}
DEV_INLINE float fast_sig(float x) {
    x = fminf(30.f, fmaxf(-30.f, x));
    return __fdividef(1.f, 1.f + __expf(-x));
}

// ---------------- cluster / mbarrier helpers --------------------------------
DEV_INLINE uint32_t smem_u32(const void* p) {
    return (uint32_t)__cvta_generic_to_shared(p);
}
DEV_INLINE uint32_t mapa_u32(uint32_t laddr, int rank) {
    uint32_t r;
    asm volatile("mapa.shared::cluster.u32 %0, %1, %2;" : "=r"(r) : "r"(laddr), "r"(rank));
    return r;
}
DEV_INLINE void mbar_init(uint32_t a, uint32_t cnt) {
    asm volatile("mbarrier.init.shared.b64 [%0], %1;" :: "r"(a), "r"(cnt) : "memory");
}
DEV_INLINE void mbar_expect_tx(uint32_t a, uint32_t tx) {
    asm volatile("mbarrier.arrive.expect_tx.shared.b64 _, [%0], %1;" :: "r"(a), "r"(tx) : "memory");
}
DEV_INLINE void mbar_wait(uint32_t a, uint32_t phase) {
    asm volatile(
        "{\n\t"
        ".reg .pred P;\n\t"
        "WL%=:\n\t"
        "mbarrier.try_wait.parity.acquire.cta.shared::cta.b64 P, [%0], %1, 0x989680;\n\t"
        "@P bra WD%=;\n\t"
        "bra WL%=;\n\t"
        "WD%=:\n\t"
        "}" :: "r"(a), "r"(phase) : "memory");
}
DEV_INLINE void st_async_b64(uint32_t raddr, ull v, uint32_t rmbar) {
    asm volatile("st.async.shared::cluster.mbarrier::complete_tx::bytes.b64 [%0], %1, [%2];"
                 :: "r"(raddr), "l"(v), "r"(rmbar) : "memory");
}
DEV_INLINE void cluster_sync_() {
    asm volatile("barrier.cluster.arrive.aligned;" ::: "memory");
    asm volatile("barrier.cluster.wait.aligned;" ::: "memory");
}

// ============================================================================
// Kernel A: conv1 (k=1 pointwise, 47->64) + tanh + frame grouping (B,1024,256)
// ============================================================================
__global__ __launch_bounds__(256) void conv1_kernel(
    const float* __restrict__ feat, const float* __restrict__ W1,
    const float* __restrict__ b1)
{
    __shared__ float sW[64 * 47];
    __shared__ float sb[64];
    __shared__ float sx[32 * 47];
    const int tid = threadIdx.x;
    const int b = blockIdx.y;
    const int f0 = blockIdx.x * 32;
    for (int i = tid; i < 64 * 47; i += 256) sW[i] = W1[i];
    if (tid < 64) sb[tid] = b1[tid];
    const float* fp = feat + ((size_t)b * 4096 + f0) * 47;
    for (int i = tid; i < 32 * 47; i += 256) sx[i] = fp[i];
    __syncthreads();
#pragma unroll
    for (int r = 0; r < 8; r++) {
        int idx = tid + 256 * r;
        int f = idx >> 6, h = idx & 63;
        float acc = sb[h];
#pragma unroll
        for (int i = 0; i < 47; i++) acc = fmaf(sx[f * 47 + i], sW[h * 47 + i], acc);
        int gf = f0 + f;
        g_c1[((size_t)b * 1024 + (gf >> 2)) * 256 + ((gf & 3) << 6) + h] = fast_tanh(acc);
    }
}

// ============================================================================
// Prep: both weight transposes in ONE kernel.
// ============================================================================
__global__ __launch_bounds__(768) void prep_kernel(
    const float* __restrict__ W2, const float* __restrict__ W_ih)
{
    int blk = blockIdx.x;
    int t = threadIdx.x;
    if (blk < 512) {
        if (t < 256)
            g_w2t[blk * 256 + t] = W2[t * 512 + ((blk & 255) << 1) + (blk >> 8)];
    } else {
        int c = blk - 512;                 // 0..255
        g_wihT[c * 768 + t] = W_ih[t * 256 + c];
    }
}

// ============================================================================
// Shared GEMM skeleton (128x128 tile, BK=16, 256 thr, 8x8 micro, f32x2 FMA)
// ============================================================================
template <int MODE>
__global__ __launch_bounds__(256) void gemm_kernel(
    const float* __restrict__ Bext, const float* __restrict__ bias)
{
    __shared__ float As[16][136];
    __shared__ float Bs[16][128];
    const int tid = threadIdx.x;
    const int tx = tid & 15, ty = tid >> 4;
    const int m0 = blockIdx.x * 128;
    const int n0 = blockIdx.y * 128;
    constexpr int K   = (MODE == 0) ? 512 : 256;
    constexpr int Nld = (MODE == 0) ? 256 : (MODE == 1 ? 1024 : 768);
    const float* Bm = (MODE == 0) ? g_w2t : (MODE == 1 ? Bext : g_wihT);
    const float* Amat = (MODE == 1) ? g_c2 : g_c3;

    ull acc[8][4];
#pragma unroll
    for (int i = 0; i < 8; i++)
#pragma unroll
        for (int j = 0; j < 4; j++) acc[i][j] = 0ULL;

    for (int k0 = 0; k0 < K; k0 += 16) {
#pragma unroll
        for (int it = 0; it < 2; it++) {
            int idx = tid + it * 256;
            int row = idx >> 2;
            int kq = (idx & 3) << 2;
            int m = m0 + row;
            float4 v;
            if (MODE == 0) {
                if (k0 < 256) {
                    if ((m & 1023) != 0)
                        v = *(const float4*)&g_c1[((size_t)m - 1) * 256 + k0 + kq];
                    else
                        v = make_float4(0.f, 0.f, 0.f, 0.f);
                } else {
                    v = *(const float4*)&g_c1[(size_t)m * 256 + (k0 - 256) + kq];
                }
            } else {
                v = *(const float4*)&Amat[(size_t)m * 256 + k0 + kq];
            }
            As[kq + 0][row] = v.x; As[kq + 1][row] = v.y;
            As[kq + 2][row] = v.z; As[kq + 3][row] = v.w;
        }
#pragma unroll
        for (int it = 0; it < 2; it++) {
            int idx = tid + it * 256;
            int kr = idx >> 5;
            int nq = (idx & 31) << 2;
            *(float4*)&Bs[kr][nq] = *(const float4*)&Bm[(size_t)(k0 + kr) * Nld + n0 + nq];
        }
        __syncthreads();
#pragma unroll
        for (int kk = 0; kk < 16; kk++) {
            float4 a0 = *(const float4*)&As[kk][ty * 8];
            float4 a1 = *(const float4*)&As[kk][ty * 8 + 4];
            ulonglong2 bb0 = *(const ulonglong2*)&Bs[kk][tx * 8];
            ulonglong2 bb1 = *(const ulonglong2*)&Bs[kk][tx * 8 + 4];
            ull ad[8] = {dup2(a0.x), dup2(a0.y), dup2(a0.z), dup2(a0.w),
                         dup2(a1.x), dup2(a1.y), dup2(a1.z), dup2(a1.w)};
            ull bp[4] = {bb0.x, bb0.y, bb1.x, bb1.y};
#pragma unroll
            for (int mm = 0; mm < 8; mm++)
#pragma unroll
                for (int np = 0; np < 4; np++) fma2(acc[mm][np], ad[mm], bp[np]);
        }
        __syncthreads();
    }
#pragma unroll
    for (int mm = 0; mm < 8; mm++) {
        int m = m0 + ty * 8 + mm;
#pragma unroll
        for (int np = 0; np < 4; np++) {
            float f0, f1;
            unpack2(acc[mm][np], f0, f1);
#pragma unroll
            for (int e = 0; e < 2; e++) {
                float f = e ? f1 : f0;
                int n = n0 + tx * 8 + np * 2 + e;
                if (MODE == 0) {
                    g_c2[(size_t)m * 256 + n] = fast_tanh(f + __ldg(&bias[n]));
                } else if (MODE == 1) {
                    int o = n >> 2, kcv = n & 3;
                    float v = fast_tanh(f + __ldg(&bias[o]));
                    int bb = m >> 10, t = m & 1023;
                    g_c3[((size_t)bb * 4096 + 4 * t + kcv) * 256 + o] = v;
                } else {
                    float v = f + __ldg(&bias[n]);
                    int bb = m >> 12, t = m & 4095;
                    int gate = n >> 8, ch = n & 255;
                    int sl = ch >> 5, loc = (gate << 5) + (ch & 31);
                    g_gx[((size_t)(bb * 8 + sl) * 4096 + t) * 96 + loc] = v;
                }
            }
        }
    }
}

// ============================================================================
// GRU: 4 clusters x 8 CTAs; each cluster runs FOUR interleaved batch chains.
// CTA (cl, s) owns channels [32s,32s+32) of batches {4cl..4cl+3}.
// Per step, 4 slots; slot c: wait(chain c) -> sync -> gemv(c) -> sync ->
// warp c: activation + st.async sends + out + gx prefetch (overlaps slot c+1).
// Chain c's exchange has a ~3-slot window to complete -> latency hiding.
// ============================================================================
__global__ void __cluster_dims__(8, 1, 1) __launch_bounds__(384, 1)
gru_kernel(const float* __restrict__ W_hh, const float* __restrict__ b_hh,
           float* __restrict__ out)
{
    __shared__ __align__(16) float h_buf[4][2][256];
    __shared__ float gates_s[4][96];
    __shared__ __align__(8) ull mbar[4][2];
    __shared__ uint32_t peer_base[8];
    const int tid = threadIdx.x;
    const int s = blockIdx.x & 7;
    const int cl = blockIdx.x >> 3;
    const int p = tid >> 2, kc = tid & 3;   // 96 rows x 4 K-chunks of 64
    const int grow = ((p >> 5) << 8) + (s << 5) + (p & 31);
    const int warp = tid >> 5, lane = tid & 31;

    // 64 weights per thread as 32 f32x2 regs (shared by all 4 chains)
    ull wp[32];
    const ull* Wp = (const ull*)W_hh;
#pragma unroll
    for (int j = 0; j < 32; j++) wp[j] = Wp[grow * 128 + kc * 32 + j];

    for (int i = tid; i < 4 * 2 * 256; i += 384) ((float*)h_buf)[i] = 0.f;
    const uint32_t X0 = smem_u32(&h_buf[0][0][0]);
    if (tid == 0) {
#pragma unroll
        for (int c = 0; c < 4; c++) {
            mbar_init(smem_u32(&mbar[c][0]), 1);
            mbar_init(smem_u32(&mbar[c][1]), 1);
        }
    }
    if (tid < 8) peer_base[tid] = mapa_u32(X0, tid);

    // per-act-warp (warps 0..3) state: chain = warp index
    float bhr = 0.f, bhz = 0.f, bhn = 0.f, gxr = 0.f, gxz = 0.f, gxn = 0.f;
    float hold = 0.f;
    size_t gx_base = 0;
    uint32_t dh0 = 0, dh1 = 0, dm0 = 0, dm1 = 0;  // offsets from X0
    float* out_p = out;
    if (warp < 4) {
        int myb = cl * 4 + warp;
        int ch = (s << 5) + lane;
        bhr = b_hh[ch]; bhz = b_hh[256 + ch]; bhn = b_hh[512 + ch];
        gx_base = (size_t)(myb * 8 + s) * 4096 * 96;
        gxr = g_gx[gx_base + lane];
        gxz = g_gx[gx_base + 32 + lane];
        gxn = g_gx[gx_base + 64 + lane];
        dh0 = smem_u32(&h_buf[warp][0][(s << 5) + lane]) - X0;
        dh1 = smem_u32(&h_buf[warp][1][(s << 5) + lane]) - X0;
        dm0 = smem_u32(&mbar[warp][0]) - X0;
        dm1 = smem_u32(&mbar[warp][1]) - X0;
        out_p = out + (size_t)myb * 4096 * 256 + (s << 5) + lane;
    }
    __syncthreads();
    cluster_sync_();  // all mbarriers initialized before any st.async

    int ph0 = 0, ph1 = 0;  // phases for this act-warp's chain barriers
    for (int t = 0; t < 4096; t++) {
        const int par = t & 1;
        const int bin = par ^ 1;
        const bool last = (t == 4095);
#pragma unroll
        for (int c = 0; c < 4; c++) {
            // ---- slot c: gate chain c's data, then gemv it ----
            if (warp == c && lane == 0) {
                if (t > 0) {
                    if (par) { mbar_wait(smem_u32(&mbar[c][1]), ph1); ph1 ^= 1; }
                    else     { mbar_wait(smem_u32(&mbar[c][0]), ph0); ph0 ^= 1; }
                }
                if (!last) mbar_expect_tx(smem_u32(&mbar[c][bin]), 1024);
            }
            __syncthreads();
            // ---- f32x2 gemv: row grow, h chunk [64kc,64kc+64) of chain c ----
            ull accA = 0ULL, accB = 0ULL;
            const ulonglong2* hb = (const ulonglong2*)&h_buf[c][par][kc * 64];
#pragma unroll
            for (int j = 0; j < 16; j++) {
                ulonglong2 hv = hb[j];
                fma2(accA, wp[2 * j + 0], hv.x);
                fma2(accB, wp[2 * j + 1], hv.y);
            }
            float ax, ay, bx, by;
            unpack2(accA, ax, ay); unpack2(accB, bx, by);
            float r0 = (ax + ay) + (bx + by);
            r0 += __shfl_xor_sync(0xffffffffu, r0, 1);
            r0 += __shfl_xor_sync(0xffffffffu, r0, 2);
            if (kc == 0) gates_s[c][p] = r0;
            __syncthreads();
            // ---- warp c: activation + exchange (overlaps slot c+1) ----
            if (warp == c) {
                float dr = gates_s[c][lane] + bhr;
                float dz = gates_s[c][32 + lane] + bhz;
                float dn = gates_s[c][64 + lane] + bhn;
                float r = fast_sig(gxr + dr);
                float z = fast_sig(gxz + dz);
                float n = fast_tanh(gxn + r * dn);
                float hnew = fmaf(z, hold - n, n);
                hold = hnew;
                float hpart = __shfl_down_sync(0xffffffffu, hnew, 1);
                if (((lane & 1) == 0) && !last) {
                    ull v2 = pack2(hnew, hpart);
                    uint32_t dh = bin ? dh1 : dh0;
                    uint32_t dm = bin ? dm1 : dm0;
#pragma unroll
                    for (int pr = 0; pr < 8; pr++)
                        st_async_b64(peer_base[pr] + dh, v2, peer_base[pr] + dm);
                }
                out_p[(size_t)t * 256] = hnew;
                int tn = last ? t : (t + 1);
                size_t off = gx_base + (size_t)tn * 96;
                gxr = __ldg(&g_gx[off + lane]);
                gxz = __ldg(&g_gx[off + 32 + lane]);
                gxn = __ldg(&g_gx[off + 64 + lane]);
            }
        }
    }
    cluster_sync_();  // no CTA exits while peers may still target its smem
}

// ============================================================================
extern "C" void kernel_launch(void* const* d_in, const int* in_sizes, int n_in,
                              void* d_out, int out_size)
{
    const float* features = (const float*)d_in[0];
    const float* W1   = (const float*)d_in[1];
    const float* b1   = (const float*)d_in[2];
    const float* W2   = (const float*)d_in[3];
    const float* b2   = (const float*)d_in[4];
    const float* Wt   = (const float*)d_in[5];
    const float* bt   = (const float*)d_in[6];
    const float* W_ih = (const float*)d_in[7];
    const float* W_hh = (const float*)d_in[8];
    const float* b_ih = (const float*)d_in[9];
    const float* b_hh = (const float*)d_in[10];
    float* out = (float*)d_out;

    conv1_kernel<<<dim3(128, 16), 256>>>(features, W1, b1);
    prep_kernel<<<768, 768>>>(W2, W_ih);
    gemm_kernel<0><<<dim3(128, 2), 256>>>(nullptr, b2);
    gemm_kernel<1><<<dim3(128, 8), 256>>>(Wt, bt);
    gemm_kernel<2><<<dim3(512, 6), 256>>>(nullptr, b_ih);
    gru_kernel<<<32, 384>>>(W_hh, b_hh, out);
}

// round 7
// speedup vs baseline: 1.2395x; 1.2395x over previous
#include <cuda_runtime.h>
#include <cstdint>

#define DEV_INLINE __device__ __forceinline__
typedef unsigned long long ull;

// ---------------- scratch (device globals; no allocations allowed) ----------
__device__ float g_c1[16 * 1024 * 256];            // after conv1 + frame grouping
__device__ float g_c2[16 * 1024 * 256];            // after conv2
__device__ float g_c3[16 * 4096 * 256];            // after tconv
__device__ float g_gx[(size_t)16 * 8 * 4096 * 96]; // gates_x, GRU-CTA-sliced layout
__device__ float g_w2t[512 * 256];                 // W2 transposed: [kk][o]
__device__ float g_wihT[256 * 768];                // W_ih transposed: [c][g]

// ---------------- packed f32x2 helpers --------------------------------------
DEV_INLINE ull dup2(float x) {
    ull r; asm("mov.b64 %0, {%1, %1};" : "=l"(r) : "f"(x)); return r;
}
DEV_INLINE void fma2(ull& d, ull a, ull b) {
    asm("fma.rn.f32x2 %0, %1, %2, %0;" : "+l"(d) : "l"(a), "l"(b));
}
DEV_INLINE void unpack2(ull v, float& x, float& y) {
    asm("mov.b64 {%0, %1}, %2;" : "=f"(x), "=f"(y) : "l"(v));
}
DEV_INLINE ull pack2(float x, float y) {
    ull r; asm("mov.b64 %0, {%1, %2};" : "=l"(r) : "f"(x), "f"(y)); return r;
}

// ---------------- fast activations (MUFU ex2 + rcp; rel err ~1e-6) ----------
DEV_INLINE float fast_tanh(float x) {
    x = fminf(15.f, fmaxf(-15.f, x));
    float e = __expf(2.f * x);
    return __fdividef(e - 1.f, e + 1.f);
}
DEV_INLINE float fast_sig(float x) {
    x = fminf(30.f, fmaxf(-30.f, x));
    return __fdividef(1.f, 1.f + __expf(-x));
}

// ---------------- cluster / mbarrier helpers (LSU path, NO async proxy) -----
DEV_INLINE uint32_t smem_u32(const void* p) {
    return (uint32_t)__cvta_generic_to_shared(p);
}
DEV_INLINE uint32_t mapa_u32(uint32_t laddr, int rank) {
    uint32_t r;
    asm volatile("mapa.shared::cluster.u32 %0, %1, %2;" : "=r"(r) : "r"(laddr), "r"(rank));
    return r;
}
DEV_INLINE void mbar_init(uint32_t a, uint32_t cnt) {
    asm volatile("mbarrier.init.shared.b64 [%0], %1;" :: "r"(a), "r"(cnt) : "memory");
}
DEV_INLINE void mbar_wait(uint32_t a, uint32_t phase) {
    asm volatile(
        "{\n\t"
        ".reg .pred P;\n\t"
        "WL%=:\n\t"
        "mbarrier.try_wait.parity.acquire.cta.shared::cta.b64 P, [%0], %1, 0x989680;\n\t"
        "@P bra WD%=;\n\t"
        "bra WL%=;\n\t"
        "WD%=:\n\t"
        "}" :: "r"(a), "r"(phase) : "memory");
}
// plain LSU remote smem store (synchronous path, ~215 cyc flight)
DEV_INLINE void st_cluster_b64(uint32_t raddr, ull v) {
    asm volatile("st.shared::cluster.b64 [%0], %1;" :: "r"(raddr), "l"(v) : "memory");
}
// remote mbarrier arrive (count-based)
DEV_INLINE void arrive_cluster(uint32_t raddr) {
    asm volatile("mbarrier.arrive.shared::cluster.b64 _, [%0];" :: "r"(raddr) : "memory");
}
DEV_INLINE void fence_cluster() {
    asm volatile("fence.acq_rel.cluster;" ::: "memory");
}
DEV_INLINE void cluster_sync_() {
    asm volatile("barrier.cluster.arrive.aligned;" ::: "memory");
    asm volatile("barrier.cluster.wait.aligned;" ::: "memory");
}

// ============================================================================
// Kernel A: conv1 (k=1 pointwise, 47->64) + tanh + frame grouping (B,1024,256)
// ============================================================================
__global__ __launch_bounds__(256) void conv1_kernel(
    const float* __restrict__ feat, const float* __restrict__ W1,
    const float* __restrict__ b1)
{
    __shared__ float sW[64 * 47];
    __shared__ float sb[64];
    __shared__ float sx[32 * 47];
    const int tid = threadIdx.x;
    const int b = blockIdx.y;
    const int f0 = blockIdx.x * 32;
    for (int i = tid; i < 64 * 47; i += 256) sW[i] = W1[i];
    if (tid < 64) sb[tid] = b1[tid];
    const float* fp = feat + ((size_t)b * 4096 + f0) * 47;
    for (int i = tid; i < 32 * 47; i += 256) sx[i] = fp[i];
    __syncthreads();
#pragma unroll
    for (int r = 0; r < 8; r++) {
        int idx = tid + 256 * r;
        int f = idx >> 6, h = idx & 63;
        float acc = sb[h];
#pragma unroll
        for (int i = 0; i < 47; i++) acc = fmaf(sx[f * 47 + i], sW[h * 47 + i], acc);
        int gf = f0 + f;
        g_c1[((size_t)b * 1024 + (gf >> 2)) * 256 + ((gf & 3) << 6) + h] = fast_tanh(acc);
    }
}

// ============================================================================
// Prep: both weight transposes in ONE kernel.
// ============================================================================
__global__ __launch_bounds__(768) void prep_kernel(
    const float* __restrict__ W2, const float* __restrict__ W_ih)
{
    int blk = blockIdx.x;
    int t = threadIdx.x;
    if (blk < 512) {
        if (t < 256)
            g_w2t[blk * 256 + t] = W2[t * 512 + ((blk & 255) << 1) + (blk >> 8)];
    } else {
        int c = blk - 512;                 // 0..255
        g_wihT[c * 768 + t] = W_ih[t * 256 + c];
    }
}

// ============================================================================
// Shared GEMM skeleton (128x128 tile, BK=16, 256 thr, 8x8 micro, f32x2 FMA)
// ============================================================================
template <int MODE>
__global__ __launch_bounds__(256) void gemm_kernel(
    const float* __restrict__ Bext, const float* __restrict__ bias)
{
    __shared__ float As[16][136];
    __shared__ float Bs[16][128];
    const int tid = threadIdx.x;
    const int tx = tid & 15, ty = tid >> 4;
    const int m0 = blockIdx.x * 128;
    const int n0 = blockIdx.y * 128;
    constexpr int K   = (MODE == 0) ? 512 : 256;
    constexpr int Nld = (MODE == 0) ? 256 : (MODE == 1 ? 1024 : 768);
    const float* Bm = (MODE == 0) ? g_w2t : (MODE == 1 ? Bext : g_wihT);
    const float* Amat = (MODE == 1) ? g_c2 : g_c3;

    ull acc[8][4];
#pragma unroll
    for (int i = 0; i < 8; i++)
#pragma unroll
        for (int j = 0; j < 4; j++) acc[i][j] = 0ULL;

    for (int k0 = 0; k0 < K; k0 += 16) {
#pragma unroll
        for (int it = 0; it < 2; it++) {
            int idx = tid + it * 256;
            int row = idx >> 2;
            int kq = (idx & 3) << 2;
            int m = m0 + row;
            float4 v;
            if (MODE == 0) {
                if (k0 < 256) {
                    if ((m & 1023) != 0)
                        v = *(const float4*)&g_c1[((size_t)m - 1) * 256 + k0 + kq];
                    else
                        v = make_float4(0.f, 0.f, 0.f, 0.f);
                } else {
                    v = *(const float4*)&g_c1[(size_t)m * 256 + (k0 - 256) + kq];
                }
            } else {
                v = *(const float4*)&Amat[(size_t)m * 256 + k0 + kq];
            }
            As[kq + 0][row] = v.x; As[kq + 1][row] = v.y;
            As[kq + 2][row] = v.z; As[kq + 3][row] = v.w;
        }
#pragma unroll
        for (int it = 0; it < 2; it++) {
            int idx = tid + it * 256;
            int kr = idx >> 5;
            int nq = (idx & 31) << 2;
            *(float4*)&Bs[kr][nq] = *(const float4*)&Bm[(size_t)(k0 + kr) * Nld + n0 + nq];
        }
        __syncthreads();
#pragma unroll
        for (int kk = 0; kk < 16; kk++) {
            float4 a0 = *(const float4*)&As[kk][ty * 8];
            float4 a1 = *(const float4*)&As[kk][ty * 8 + 4];
            ulonglong2 bb0 = *(const ulonglong2*)&Bs[kk][tx * 8];
            ulonglong2 bb1 = *(const ulonglong2*)&Bs[kk][tx * 8 + 4];
            ull ad[8] = {dup2(a0.x), dup2(a0.y), dup2(a0.z), dup2(a0.w),
                         dup2(a1.x), dup2(a1.y), dup2(a1.z), dup2(a1.w)};
            ull bp[4] = {bb0.x, bb0.y, bb1.x, bb1.y};
#pragma unroll
            for (int mm = 0; mm < 8; mm++)
#pragma unroll
                for (int np = 0; np < 4; np++) fma2(acc[mm][np], ad[mm], bp[np]);
        }
        __syncthreads();
    }
#pragma unroll
    for (int mm = 0; mm < 8; mm++) {
        int m = m0 + ty * 8 + mm;
#pragma unroll
        for (int np = 0; np < 4; np++) {
            float f0, f1;
            unpack2(acc[mm][np], f0, f1);
#pragma unroll
            for (int e = 0; e < 2; e++) {
                float f = e ? f1 : f0;
                int n = n0 + tx * 8 + np * 2 + e;
                if (MODE == 0) {
                    g_c2[(size_t)m * 256 + n] = fast_tanh(f + __ldg(&bias[n]));
                } else if (MODE == 1) {
                    int o = n >> 2, kcv = n & 3;
                    float v = fast_tanh(f + __ldg(&bias[o]));
                    int bb = m >> 10, t = m & 1023;
                    g_c3[((size_t)bb * 4096 + 4 * t + kcv) * 256 + o] = v;
                } else {
                    float v = f + __ldg(&bias[n]);
                    int bb = m >> 12, t = m & 4095;
                    int gate = n >> 8, ch = n & 255;
                    int sl = ch >> 5, loc = (gate << 5) + (ch & 31);
                    g_gx[((size_t)(bb * 8 + sl) * 4096 + t) * 96 + loc] = v;
                }
            }
        }
    }
}

// ============================================================================
// GRU: 16 clusters x 8 CTAs. CTA (b, s) owns channels [32s, 32s+32).
// Exchange via SYNCHRONOUS LSU DSMEM path (no async proxy):
//   plain st.shared::cluster.b64 pushes -> syncwarp -> fence.acq_rel.cluster
//   -> 8 remote mbarrier arrives (count-8 barrier) -> lane-0 wait + fence.
// Double-buffered h, parity-tracked per slot.
// ============================================================================
__global__ void __cluster_dims__(8, 1, 1) __launch_bounds__(384, 1)
gru_kernel(const float* __restrict__ W_hh, const float* __restrict__ b_hh,
           float* __restrict__ out)
{
    __shared__ __align__(16) float h_buf[2][256];
    __shared__ float gates_s[96];
    __shared__ __align__(8) ull mbar[2];
    const int tid = threadIdx.x;
    const int s = blockIdx.x & 7;
    const int b = blockIdx.x >> 3;
    const int p = tid >> 2, kc = tid & 3;   // 96 rows x 4 K-chunks of 64
    const int grow = ((p >> 5) << 8) + (s << 5) + (p & 31);  // global gate row
    const int lane = tid & 31;

    // 64 weights per thread as 32 f32x2 regs
    ull wp[32];
    const ull* Wp = (const ull*)W_hh;
#pragma unroll
    for (int j = 0; j < 32; j++) wp[j] = Wp[grow * 128 + kc * 32 + j];
    if (tid < 256) h_buf[0][tid] = 0.f;

    const uint32_t mb0 = smem_u32(&mbar[0]);
    const uint32_t mb1 = smem_u32(&mbar[1]);
    if (tid == 0) { mbar_init(mb0, 8); mbar_init(mb1, 8); }  // 8 arrives/use

    const size_t gx_base = (size_t)(b * 8 + s) * 4096 * 96;
    float bhr = 0.f, bhz = 0.f, bhn = 0.f, gxr = 0.f, gxz = 0.f, gxn = 0.f;
    float hold = 0.f;
    uint32_t rh[2][8];       // even lanes: remote h-slot addresses (8 peers)
    uint32_t rmb0 = 0, rmb1 = 0;  // lanes 0-7: remote barrier of peer==lane
    if (tid < 32) {
        int ch = (s << 5) + tid;
        bhr = b_hh[ch]; bhz = b_hh[256 + ch]; bhn = b_hh[512 + ch];
        gxr = g_gx[gx_base + tid];
        gxz = g_gx[gx_base + 32 + tid];
        gxn = g_gx[gx_base + 64 + tid];
        if ((tid & 1) == 0) {
            uint32_t l0 = smem_u32(&h_buf[0][(s << 5) + tid]);
            uint32_t l1 = smem_u32(&h_buf[1][(s << 5) + tid]);
#pragma unroll
            for (int pr = 0; pr < 8; pr++) {
                rh[0][pr] = mapa_u32(l0, pr);
                rh[1][pr] = mapa_u32(l1, pr);
            }
        }
        if (tid < 8) {
            rmb0 = mapa_u32(mb0, tid);
            rmb1 = mapa_u32(mb1, tid);
        }
    }
    __syncthreads();
    cluster_sync_();  // all mbarriers initialized before any remote op

    int ph0 = 0, ph1 = 0;
    for (int t = 0; t < 4096; t++) {
        const int bin = (t + 1) & 1;      // incoming buffer for h_{t+1}
        const bool last = (t == 4095);

        // ---- f32x2 gemv: row grow, h chunk [64kc, 64kc+64) ----
        ull accA = 0ULL, accB = 0ULL;
        const ulonglong2* hb = (const ulonglong2*)&h_buf[t & 1][kc * 64];
#pragma unroll
        for (int j = 0; j < 16; j++) {
            ulonglong2 hv = hb[j];
            fma2(accA, wp[2 * j + 0], hv.x);
            fma2(accB, wp[2 * j + 1], hv.y);
        }
        float ax, ay, bx, by;
        unpack2(accA, ax, ay); unpack2(accB, bx, by);
        float r0 = (ax + ay) + (bx + by);
        r0 += __shfl_xor_sync(0xffffffffu, r0, 1);
        r0 += __shfl_xor_sync(0xffffffffu, r0, 2);
        if (kc == 0) gates_s[p] = r0;
        __syncthreads();

        if (tid < 32) {
            float dr = gates_s[tid] + bhr;
            float dz = gates_s[32 + tid] + bhz;
            float dn = gates_s[64 + tid] + bhn;
            float r = fast_sig(gxr + dr);
            float z = fast_sig(gxz + dz);
            float n = fast_tanh(gxn + r * dn);
            float hnew = fmaf(z, hold - n, n);  // (1-z)n + z*h
            hold = hnew;
            // pack adjacent-lane pairs; even lanes push b64 to all 8 peers
            float hpart = __shfl_down_sync(0xffffffffu, hnew, 1);
            if (!last) {
                if ((tid & 1) == 0) {
                    ull v2 = pack2(hnew, hpart);
#pragma unroll
                    for (int pr = 0; pr < 8; pr++)
                        st_cluster_b64(rh[bin][pr], v2);
                }
                __syncwarp();
                fence_cluster();                 // order stores before arrives
                if (tid < 8)
                    arrive_cluster(bin ? rmb1 : rmb0);
            }
            out[((size_t)b * 4096 + t) * 256 + (s << 5) + tid] = hnew;
            // prefetch next step's x-gates (off critical path)
            int tn = last ? t : (t + 1);
            size_t off = gx_base + (size_t)tn * 96;
            gxr = __ldg(&g_gx[off + tid]);
            gxz = __ldg(&g_gx[off + 32 + tid]);
            gxn = __ldg(&g_gx[off + 64 + tid]);
        }
        // ---- single-lane wait; everyone else parks at the barrier ----
        if (tid == 0 && !last) {
            if (bin) { mbar_wait(mb1, ph1); ph1 ^= 1; }
            else     { mbar_wait(mb0, ph0); ph0 ^= 1; }
            fence_cluster();                     // acquire peers' stores
        }
        __syncthreads();
    }
    cluster_sync_();  // no CTA exits while peers may still target its smem
}

// ============================================================================
extern "C" void kernel_launch(void* const* d_in, const int* in_sizes, int n_in,
                              void* d_out, int out_size)
{
    const float* features = (const float*)d_in[0];
    const float* W1   = (const float*)d_in[1];
    const float* b1   = (const float*)d_in[2];
    const float* W2   = (const float*)d_in[3];
    const float* b2   = (const float*)d_in[4];
    const float* Wt   = (const float*)d_in[5];
    const float* bt   = (const float*)d_in[6];
    const float* W_ih = (const float*)d_in[7];
    const float* W_hh = (const float*)d_in[8];
    const float* b_ih = (const float*)d_in[9];
    const float* b_hh = (const float*)d_in[10];
    float* out = (float*)d_out;

    conv1_kernel<<<dim3(128, 16), 256>>>(features, W1, b1);
    prep_kernel<<<768, 768>>>(W2, W_ih);
    gemm_kernel<0><<<dim3(128, 2), 256>>>(nullptr, b2);
    gemm_kernel<1><<<dim3(128, 8), 256>>>(Wt, bt);
    gemm_kernel<2><<<dim3(512, 6), 256>>>(nullptr, b_ih);
    gru_kernel<<<128, 384>>>(W_hh, b_hh, out);
}